// round 1
// baseline (speedup 1.0000x reference)
#include <cuda_runtime.h>

// Problem constants
#define DM 256
#define NH 4
#define DH 64
#define BB 4
#define TT 512
#define SS 512
#define BHN 16   // B*H

// Scratch (no allocs allowed -> device globals)
__device__ float g_Q[BHN * TT * DH];   // [bh][t][d]
__device__ float g_K[BHN * SS * DH];   // [bh][s][d]
__device__ float g_V[BHN * SS * DH];   // [bh][s][d]
__device__ float g_att[BB * TT * DM];  // attended, [b][t][h*64+d]

__device__ __forceinline__ float tanh_fast(float x) {
    float y;
    asm("tanh.approx.f32 %0, %1;" : "=f"(y) : "f"(x));
    return y;
}

// ---------------------------------------------------------------------------
// GEMM: C[m][n] = sum_k A[m][k] * W[n][k]   (x @ W.T, W stored (out,in))
// M=2048, N=256, K=256. 64x64 tile, BK=16, 256 threads, 4x4 micro-tile.
// mode 0/1/2: write to g_Q/g_K/g_V in [bh][t][d] layout.
// mode 3:     A := g_att, write plain row-major to C (final output).
// ---------------------------------------------------------------------------
__global__ __launch_bounds__(256) void gemm_xwT(const float* __restrict__ A_in,
                                                const float* __restrict__ W,
                                                float* __restrict__ C, int mode) {
    const float* A = (mode == 3) ? g_att : A_in;
    const int m0 = blockIdx.x * 64;
    const int n0 = blockIdx.y * 64;

    __shared__ float Ast[16 * 68];  // [k][m], pitch 68 floats
    __shared__ float Wst[16 * 68];  // [k][n]

    const int tid = threadIdx.x;
    const int tx = tid & 15;   // n/4
    const int ty = tid >> 4;   // m/4

    float acc[4][4] = {};

    for (int k0 = 0; k0 < DM; k0 += 16) {
#pragma unroll
        for (int i = 0; i < 4; i++) {
            int idx = tid + i * 256;          // 0..1023
            int r = idx >> 4;                 // 0..63 (m or n within tile)
            int c = idx & 15;                 // 0..15 (k)
            Ast[c * 68 + r] = A[(size_t)(m0 + r) * DM + k0 + c];
            Wst[c * 68 + r] = W[(size_t)(n0 + r) * DM + k0 + c];
        }
        __syncthreads();
#pragma unroll
        for (int kk = 0; kk < 16; kk++) {
            float4 a4 = *(const float4*)&Ast[kk * 68 + ty * 4];
            float4 w4 = *(const float4*)&Wst[kk * 68 + tx * 4];
            acc[0][0] += a4.x * w4.x; acc[0][1] += a4.x * w4.y;
            acc[0][2] += a4.x * w4.z; acc[0][3] += a4.x * w4.w;
            acc[1][0] += a4.y * w4.x; acc[1][1] += a4.y * w4.y;
            acc[1][2] += a4.y * w4.z; acc[1][3] += a4.y * w4.w;
            acc[2][0] += a4.z * w4.x; acc[2][1] += a4.z * w4.y;
            acc[2][2] += a4.z * w4.z; acc[2][3] += a4.z * w4.w;
            acc[3][0] += a4.w * w4.x; acc[3][1] += a4.w * w4.y;
            acc[3][2] += a4.w * w4.z; acc[3][3] += a4.w * w4.w;
        }
        __syncthreads();
    }

    if (mode < 3) {
        float* dst = (mode == 0) ? g_Q : (mode == 1) ? g_K : g_V;
        const int hh = n0 >> 6;       // head index (tile never crosses a head: 64|n0)
        const int d = tx * 4;         // d within head
#pragma unroll
        for (int i = 0; i < 4; i++) {
            int m = m0 + ty * 4 + i;
            int bb = m >> 9;          // batch
            int t = m & 511;
            float4 v = make_float4(acc[i][0], acc[i][1], acc[i][2], acc[i][3]);
            *(float4*)&dst[((size_t)(bb * NH + hh) * TT + t) * DH + d] = v;
        }
    } else {
#pragma unroll
        for (int i = 0; i < 4; i++) {
            int m = m0 + ty * 4 + i;
            float4 v = make_float4(acc[i][0], acc[i][1], acc[i][2], acc[i][3]);
            *(float4*)&C[(size_t)m * DM + n0 + tx * 4] = v;
        }
    }
}

// ---------------------------------------------------------------------------
// Scores: raw_score[bh][t][s] = SCALE * sum_d v_a[h][d] * tanh(Q[t][d]+K[s][d])
// Block: 256 threads = 8 warps, handles (bh, 32 t-rows, 128 s-cols).
// Thread's t = lane (Q row from padded smem, conflict-free float4);
// warp w handles s = s0 + w*16 + j ; K row is a uniform (broadcast) LDG.128.
// Writes raw scores into the attn output region (softmaxed in-place later).
// ---------------------------------------------------------------------------
__global__ __launch_bounds__(256) void scores_kernel(const float* __restrict__ v_a,
                                                     float* __restrict__ attn) {
    const int bh = blockIdx.x;
    const int t0 = blockIdx.y * 32;
    const int s0 = blockIdx.z * 128;
    const int h = bh & 3;

    __shared__ float qs[32 * 68];     // Q tile [t][d], pitch 68
    __shared__ float vas[64];
    __shared__ float sc[32 * 129];    // score tile [t][s_local], pitch 129

    const int tid = threadIdx.x;
    const int lane = tid & 31;
    const int w = tid >> 5;

    // Load Q tile: 32x64 floats = 512 float4
    {
        const float4* Qg = (const float4*)(g_Q + ((size_t)bh * TT + t0) * DH);
        for (int i = tid; i < 512; i += 256) {
            int r = i >> 4, c = i & 15;
            *(float4*)&qs[r * 68 + c * 4] = Qg[r * 16 + c];
        }
    }
    if (tid < 16) ((float4*)vas)[tid] = ((const float4*)(v_a + h * DH))[tid];
    __syncthreads();

    const float* qrow = &qs[lane * 68];

    for (int j = 0; j < 16; j++) {
        int sl = w * 16 + j;
        const float4* Kg = (const float4*)(g_K + ((size_t)bh * SS + s0 + sl) * DH);
        float acc = 0.f;
#pragma unroll
        for (int i = 0; i < 16; i++) {
            float4 k4 = Kg[i];                               // uniform per warp
            float4 q4 = *(const float4*)&qrow[i * 4];        // conflict-free
            float4 v4 = ((const float4*)vas)[i];             // broadcast
            acc += v4.x * tanh_fast(q4.x + k4.x);
            acc += v4.y * tanh_fast(q4.y + k4.y);
            acc += v4.z * tanh_fast(q4.z + k4.z);
            acc += v4.w * tanh_fast(q4.w + k4.w);
        }
        sc[lane * 129 + sl] = acc * 0.125f;   // SCALE = 1/sqrt(64)
    }
    __syncthreads();

    // Coalesced writeback of the 32x128 tile
    float* arow = attn + ((size_t)bh * TT + t0) * SS + s0;
    for (int i = tid; i < 32 * 128; i += 256) {
        int r = i >> 7, c = i & 127;
        arow[(size_t)r * SS + c] = sc[r * 129 + c];
    }
}

// ---------------------------------------------------------------------------
// Softmax in-place over the last dim (S=512). One block (128 thr) per row.
// ---------------------------------------------------------------------------
__global__ __launch_bounds__(128) void softmax_kernel(float* __restrict__ attn) {
    const int row = blockIdx.x;               // 0..8191
    float4* p = (float4*)(attn + (size_t)row * SS);
    const int tid = threadIdx.x;

    __shared__ float rmax[4], rsum[4];

    float4 v = p[tid];
    float m = fmaxf(fmaxf(v.x, v.y), fmaxf(v.z, v.w));
#pragma unroll
    for (int o = 16; o; o >>= 1) m = fmaxf(m, __shfl_xor_sync(0xffffffffu, m, o));
    if ((tid & 31) == 0) rmax[tid >> 5] = m;
    __syncthreads();
    m = fmaxf(fmaxf(rmax[0], rmax[1]), fmaxf(rmax[2], rmax[3]));

    v.x = __expf(v.x - m);
    v.y = __expf(v.y - m);
    v.z = __expf(v.z - m);
    v.w = __expf(v.w - m);
    float s = v.x + v.y + v.z + v.w;
#pragma unroll
    for (int o = 16; o; o >>= 1) s += __shfl_xor_sync(0xffffffffu, s, o);
    __syncthreads();   // protect rmax reads before reusing pattern (paranoia) / order rsum writes
    if ((tid & 31) == 0) rsum[tid >> 5] = s;
    __syncthreads();
    float inv = 1.0f / (rsum[0] + rsum[1] + rsum[2] + rsum[3]);

    v.x *= inv; v.y *= inv; v.z *= inv; v.w *= inv;
    p[tid] = v;
}

// ---------------------------------------------------------------------------
// attended[b][t][h*64+d] = sum_s attn[bh][t][s] * V[bh][s][d]
// Batched GEMM: per block (bh, 32 t-rows) x full 64 d. 128 threads, 4x4 micro.
// ---------------------------------------------------------------------------
__global__ __launch_bounds__(128) void av_kernel(const float* __restrict__ attn) {
    const int bh = blockIdx.x;
    const int t0 = blockIdx.y * 32;

    __shared__ float As[32 * 33];   // attn tile [t][s]
    __shared__ float Bs[32 * 68];   // V tile    [s][d]

    const int tid = threadIdx.x;
    const int tx = tid & 15;   // d/4
    const int ty = tid >> 4;   // t/4  (0..7)

    float acc[4][4] = {};
    const float* Ag = attn + ((size_t)bh * TT + t0) * SS;
    const float* Vg = g_V + (size_t)bh * SS * DH;

    for (int s0 = 0; s0 < SS; s0 += 32) {
        for (int i = tid; i < 1024; i += 128) {
            int r = i >> 5, c = i & 31;
            As[r * 33 + c] = Ag[(size_t)r * SS + s0 + c];
        }
        for (int i = tid; i < 512; i += 128) {
            int r = i >> 4, c = i & 15;
            *(float4*)&Bs[r * 68 + c * 4] = *(const float4*)&Vg[(size_t)(s0 + r) * DH + c * 4];
        }
        __syncthreads();
#pragma unroll
        for (int kk = 0; kk < 32; kk++) {
            float4 b4 = *(const float4*)&Bs[kk * 68 + tx * 4];
            float a0 = As[(ty * 4 + 0) * 33 + kk];
            float a1 = As[(ty * 4 + 1) * 33 + kk];
            float a2 = As[(ty * 4 + 2) * 33 + kk];
            float a3 = As[(ty * 4 + 3) * 33 + kk];
            acc[0][0] += a0 * b4.x; acc[0][1] += a0 * b4.y; acc[0][2] += a0 * b4.z; acc[0][3] += a0 * b4.w;
            acc[1][0] += a1 * b4.x; acc[1][1] += a1 * b4.y; acc[1][2] += a1 * b4.z; acc[1][3] += a1 * b4.w;
            acc[2][0] += a2 * b4.x; acc[2][1] += a2 * b4.y; acc[2][2] += a2 * b4.z; acc[2][3] += a2 * b4.w;
            acc[3][0] += a3 * b4.x; acc[3][1] += a3 * b4.y; acc[3][2] += a3 * b4.z; acc[3][3] += a3 * b4.w;
        }
        __syncthreads();
    }

    const int b = bh >> 2, h = bh & 3;
#pragma unroll
    for (int i = 0; i < 4; i++) {
        int t = t0 + ty * 4 + i;
        float4 v = make_float4(acc[i][0], acc[i][1], acc[i][2], acc[i][3]);
        *(float4*)&g_att[((size_t)(b * TT + t)) * DM + h * DH + tx * 4] = v;
    }
}

// ---------------------------------------------------------------------------
// Launch
// ---------------------------------------------------------------------------
extern "C" void kernel_launch(void* const* d_in, const int* in_sizes, int n_in,
                              void* d_out, int out_size) {
    const float* query = (const float*)d_in[0];
    const float* key   = (const float*)d_in[1];
    const float* value = (const float*)d_in[2];
    const float* w_q   = (const float*)d_in[3];
    const float* w_k   = (const float*)d_in[4];
    const float* w_v   = (const float*)d_in[5];
    const float* v_a   = (const float*)d_in[6];
    const float* w_o   = (const float*)d_in[7];

    float* out  = (float*)d_out;                       // [B,T,DM] = 524288 floats
    float* attn = out + (size_t)BB * TT * DM;          // [B,H,T,S] = 4194304 floats

    dim3 gg(32, 4);
    // Projections -> g_Q / g_K / g_V in [bh][t/s][d] layout
    gemm_xwT<<<gg, 256>>>(query, w_q, nullptr, 0);
    gemm_xwT<<<gg, 256>>>(key,   w_k, nullptr, 1);
    gemm_xwT<<<gg, 256>>>(value, w_v, nullptr, 2);

    // Additive scores (raw) directly into attn output region
    scores_kernel<<<dim3(BHN, TT / 32, SS / 128), 256>>>(v_a, attn);

    // Softmax in place
    softmax_kernel<<<BHN * TT, 128>>>(attn);

    // attended = attn @ V  -> g_att in [b][t][h*64+d] layout
    av_kernel<<<dim3(BHN, TT / 32), 128>>>(attn);

    // out = attended @ w_o.T
    gemm_xwT<<<gg, 256>>>(nullptr, w_o, out, 3);
}

// round 2
// speedup vs baseline: 1.1621x; 1.1621x over previous
#include <cuda_runtime.h>

#define DM 256
#define NH 4
#define DH 64
#define BB 4
#define TT 512
#define SS 512
#define BHN 16

// Scratch (no allocs allowed -> device globals)
__device__ float g_Q[BHN * TT * DH];   // [bh][t][d]
__device__ float g_K[BHN * SS * DH];   // [bh][s][d]
__device__ float g_V[BHN * SS * DH];   // [bh][s][d]
__device__ float g_att[BB * TT * DM];  // attended, [b][t][h*64+d]

__device__ __forceinline__ float tanh_fast(float x) {
    float y;
    asm("tanh.approx.f32 %0, %1;" : "=f"(y) : "f"(x));
    return y;
}

// ---- packed f32x2 helpers (sm_100a) --------------------------------------
__device__ __forceinline__ unsigned long long pack2(float x, float y) {
    unsigned long long r;
    asm("mov.b64 %0, {%1, %2};" : "=l"(r) : "f"(x), "f"(y));
    return r;
}
__device__ __forceinline__ float2 unpack2(unsigned long long v) {
    float2 r;
    asm("mov.b64 {%0, %1}, %2;" : "=f"(r.x), "=f"(r.y) : "l"(v));
    return r;
}
__device__ __forceinline__ unsigned long long fma2(unsigned long long a,
                                                   unsigned long long b,
                                                   unsigned long long c) {
    unsigned long long d;
    asm("fma.rn.f32x2 %0, %1, %2, %3;" : "=l"(d) : "l"(a), "l"(b), "l"(c));
    return d;
}

// ---------------------------------------------------------------------------
// GEMM body: 64x64 tile, BK=16, 128 threads, micro 8(m)x4(n) with f32x2 FMA.
// Computes C[m][n] = sum_k A[m][k]*W[n][k].
// ---------------------------------------------------------------------------
struct GemmAcc { unsigned long long a[8][2]; };

__device__ __forceinline__ void gemm_body(const float* __restrict__ A,
                                          const float* __restrict__ W,
                                          int m0, int n0, GemmAcc& G,
                                          float* Ast, float* Wst) {
    const int tid = threadIdx.x;
    const int tx = tid & 15;    // n/4
    const int tyy = tid >> 4;   // m/8  (0..7)

#pragma unroll
    for (int i = 0; i < 8; i++) { G.a[i][0] = 0ull; G.a[i][1] = 0ull; }

    for (int k0 = 0; k0 < DM; k0 += 16) {
#pragma unroll
        for (int i = tid; i < 1024; i += 128) {
            int r = i >> 4, c = i & 15;
            Ast[c * 68 + r] = A[(size_t)(m0 + r) * DM + k0 + c];
            Wst[c * 68 + r] = W[(size_t)(n0 + r) * DM + k0 + c];
        }
        __syncthreads();
#pragma unroll
        for (int kk = 0; kk < 16; kk++) {
            ulonglong2 w2 = *(const ulonglong2*)&Wst[kk * 68 + tx * 4];
            float4 a0 = *(const float4*)&Ast[kk * 68 + tyy * 8];
            float4 a1 = *(const float4*)&Ast[kk * 68 + tyy * 8 + 4];
            unsigned long long aa;
            aa = pack2(a0.x, a0.x); G.a[0][0] = fma2(aa, w2.x, G.a[0][0]); G.a[0][1] = fma2(aa, w2.y, G.a[0][1]);
            aa = pack2(a0.y, a0.y); G.a[1][0] = fma2(aa, w2.x, G.a[1][0]); G.a[1][1] = fma2(aa, w2.y, G.a[1][1]);
            aa = pack2(a0.z, a0.z); G.a[2][0] = fma2(aa, w2.x, G.a[2][0]); G.a[2][1] = fma2(aa, w2.y, G.a[2][1]);
            aa = pack2(a0.w, a0.w); G.a[3][0] = fma2(aa, w2.x, G.a[3][0]); G.a[3][1] = fma2(aa, w2.y, G.a[3][1]);
            aa = pack2(a1.x, a1.x); G.a[4][0] = fma2(aa, w2.x, G.a[4][0]); G.a[4][1] = fma2(aa, w2.y, G.a[4][1]);
            aa = pack2(a1.y, a1.y); G.a[5][0] = fma2(aa, w2.x, G.a[5][0]); G.a[5][1] = fma2(aa, w2.y, G.a[5][1]);
            aa = pack2(a1.z, a1.z); G.a[6][0] = fma2(aa, w2.x, G.a[6][0]); G.a[6][1] = fma2(aa, w2.y, G.a[6][1]);
            aa = pack2(a1.w, a1.w); G.a[7][0] = fma2(aa, w2.x, G.a[7][0]); G.a[7][1] = fma2(aa, w2.y, G.a[7][1]);
        }
        __syncthreads();
    }
}

// Projections: blockIdx.z selects (query,w_q)->g_Q, (key,w_k)->g_K, (value,w_v)->g_V
__global__ __launch_bounds__(128) void proj_kernel(const float* __restrict__ q_in,
                                                   const float* __restrict__ k_in,
                                                   const float* __restrict__ v_in,
                                                   const float* __restrict__ w_q,
                                                   const float* __restrict__ w_k,
                                                   const float* __restrict__ w_v) {
    __shared__ float Ast[16 * 68];
    __shared__ float Wst[16 * 68];
    const int which = blockIdx.z;
    const float* A = (which == 0) ? q_in : (which == 1) ? k_in : v_in;
    const float* W = (which == 0) ? w_q : (which == 1) ? w_k : w_v;
    float* dst = (which == 0) ? g_Q : (which == 1) ? g_K : g_V;
    const int m0 = blockIdx.x * 64;
    const int n0 = blockIdx.y * 64;

    GemmAcc G;
    gemm_body(A, W, m0, n0, G, Ast, Wst);

    const int tx = threadIdx.x & 15;
    const int tyy = threadIdx.x >> 4;
    const int hh = n0 >> 6;
#pragma unroll
    for (int i = 0; i < 8; i++) {
        int m = m0 + tyy * 8 + i;
        int bb = m >> 9, t = m & 511;
        float2 c01 = unpack2(G.a[i][0]);
        float2 c23 = unpack2(G.a[i][1]);
        *(float4*)&dst[((size_t)(bb * NH + hh) * TT + t) * DH + tx * 4] =
            make_float4(c01.x, c01.y, c23.x, c23.y);
    }
}

// Output projection: out = g_att @ w_o.T
__global__ __launch_bounds__(128) void out_kernel(const float* __restrict__ w_o,
                                                  float* __restrict__ C) {
    __shared__ float Ast[16 * 68];
    __shared__ float Wst[16 * 68];
    const int m0 = blockIdx.x * 64;
    const int n0 = blockIdx.y * 64;

    GemmAcc G;
    gemm_body(g_att, w_o, m0, n0, G, Ast, Wst);

    const int tx = threadIdx.x & 15;
    const int tyy = threadIdx.x >> 4;
#pragma unroll
    for (int i = 0; i < 8; i++) {
        int m = m0 + tyy * 8 + i;
        float2 c01 = unpack2(G.a[i][0]);
        float2 c23 = unpack2(G.a[i][1]);
        *(float4*)&C[(size_t)m * DM + n0 + tx * 4] =
            make_float4(c01.x, c01.y, c23.x, c23.y);
    }
}

// ---------------------------------------------------------------------------
// Scores: raw[bh][t][s] = 0.125 * sum_d v_a[h][d] * tanh(Q[t][d]+K[s][d])
// 256 threads / block; tile (32 t) x (128 s). Warp w owns 16 s, processed as
// 4 groups of 4 (4 independent accumulator chains, q/v_a loads amortized 4x).
// ---------------------------------------------------------------------------
__global__ __launch_bounds__(256, 3) void scores_kernel(const float* __restrict__ v_a,
                                                        float* __restrict__ attn) {
    const int bh = blockIdx.x;
    const int t0 = blockIdx.y * 32;
    const int s0 = blockIdx.z * 128;
    const int h = bh & 3;

    __shared__ float qs[32 * 68];     // [t][d] pitch 68
    __shared__ float vas[64];
    __shared__ float sc[32 * 132];    // [t][s_local] pitch 132 (float4-safe)

    const int tid = threadIdx.x;
    const int lane = tid & 31;
    const int w = tid >> 5;

    {
        const float4* Qg = (const float4*)(g_Q + ((size_t)bh * TT + t0) * DH);
        for (int i = tid; i < 512; i += 256) {
            int r = i >> 4, c = i & 15;
            *(float4*)&qs[r * 68 + c * 4] = Qg[r * 16 + c];
        }
    }
    if (tid < 16) ((float4*)vas)[tid] = ((const float4*)(v_a + h * DH))[tid];
    __syncthreads();

    const float* qrow = &qs[lane * 68];

#pragma unroll 1
    for (int g = 0; g < 4; g++) {
        const int sl = w * 16 + g * 4;
        const float4* K0 = (const float4*)(g_K + ((size_t)bh * SS + s0 + sl) * DH);
        const float4* K1 = K0 + 16;
        const float4* K2 = K0 + 32;
        const float4* K3 = K0 + 48;
        float a0 = 0.f, a1 = 0.f, a2 = 0.f, a3 = 0.f;
#pragma unroll
        for (int i = 0; i < 16; i++) {
            float4 q4 = *(const float4*)&qrow[i * 4];
            float4 v4 = ((const float4*)vas)[i];
            float4 k0 = K0[i], k1 = K1[i], k2 = K2[i], k3 = K3[i];
            a0 += v4.x * tanh_fast(q4.x + k0.x) + v4.y * tanh_fast(q4.y + k0.y)
                + v4.z * tanh_fast(q4.z + k0.z) + v4.w * tanh_fast(q4.w + k0.w);
            a1 += v4.x * tanh_fast(q4.x + k1.x) + v4.y * tanh_fast(q4.y + k1.y)
                + v4.z * tanh_fast(q4.z + k1.z) + v4.w * tanh_fast(q4.w + k1.w);
            a2 += v4.x * tanh_fast(q4.x + k2.x) + v4.y * tanh_fast(q4.y + k2.y)
                + v4.z * tanh_fast(q4.z + k2.z) + v4.w * tanh_fast(q4.w + k2.w);
            a3 += v4.x * tanh_fast(q4.x + k3.x) + v4.y * tanh_fast(q4.y + k3.y)
                + v4.z * tanh_fast(q4.z + k3.z) + v4.w * tanh_fast(q4.w + k3.w);
        }
        *(float4*)&sc[lane * 132 + sl] =
            make_float4(a0 * 0.125f, a1 * 0.125f, a2 * 0.125f, a3 * 0.125f);
    }
    __syncthreads();

    float* arow = attn + ((size_t)bh * TT + t0) * SS + s0;
    for (int i = tid; i < 32 * 128; i += 256) {
        int r = i >> 7, c = i & 127;
        arow[(size_t)r * SS + c] = sc[r * 132 + c];
    }
}

// ---------------------------------------------------------------------------
// Fused softmax + AV. Block = (bh, 32 t rows). Raw scores -> smem -> softmax
// -> attn writeback -> attended = attn @ V (f32x2 FMA), into g_att.
// Dynamic smem: sc 32x516 + Bs 32x68.
// ---------------------------------------------------------------------------
#define SCP 516
__global__ __launch_bounds__(256) void softmax_av_kernel(float* __restrict__ attn) {
    extern __shared__ float sm[];
    float* sc = sm;                  // 32*516
    float* Bs = sm + 32 * SCP;       // 32*68

    const int bh = blockIdx.x;
    const int t0 = blockIdx.y * 32;
    const int tid = threadIdx.x;
    const int lane = tid & 31;
    const int w = tid >> 5;

    float* arow = attn + ((size_t)bh * TT + t0) * SS;

    // load raw scores
    for (int i = tid; i < 32 * 128; i += 256) {
        int r = i >> 7, c = i & 127;
        *(float4*)&sc[r * SCP + c * 4] = *(const float4*)&arow[(size_t)r * SS + c * 4];
    }
    __syncthreads();

    // softmax: warp w handles rows w*4 .. w*4+3
#pragma unroll 1
    for (int q = 0; q < 4; q++) {
        int r = w * 4 + q;
        float4* row = (float4*)&sc[r * SCP];
        float4 x0 = row[lane], x1 = row[lane + 32], x2 = row[lane + 64], x3 = row[lane + 96];
        float m = fmaxf(fmaxf(fmaxf(x0.x, x0.y), fmaxf(x0.z, x0.w)),
                        fmaxf(fmaxf(x1.x, x1.y), fmaxf(x1.z, x1.w)));
        m = fmaxf(m, fmaxf(fmaxf(fmaxf(x2.x, x2.y), fmaxf(x2.z, x2.w)),
                           fmaxf(fmaxf(x3.x, x3.y), fmaxf(x3.z, x3.w))));
#pragma unroll
        for (int o = 16; o; o >>= 1) m = fmaxf(m, __shfl_xor_sync(0xffffffffu, m, o));
        x0.x = __expf(x0.x - m); x0.y = __expf(x0.y - m); x0.z = __expf(x0.z - m); x0.w = __expf(x0.w - m);
        x1.x = __expf(x1.x - m); x1.y = __expf(x1.y - m); x1.z = __expf(x1.z - m); x1.w = __expf(x1.w - m);
        x2.x = __expf(x2.x - m); x2.y = __expf(x2.y - m); x2.z = __expf(x2.z - m); x2.w = __expf(x2.w - m);
        x3.x = __expf(x3.x - m); x3.y = __expf(x3.y - m); x3.z = __expf(x3.z - m); x3.w = __expf(x3.w - m);
        float s = (x0.x + x0.y + x0.z + x0.w) + (x1.x + x1.y + x1.z + x1.w)
                + (x2.x + x2.y + x2.z + x2.w) + (x3.x + x3.y + x3.z + x3.w);
#pragma unroll
        for (int o = 16; o; o >>= 1) s += __shfl_xor_sync(0xffffffffu, s, o);
        float inv = 1.0f / s;
        x0.x *= inv; x0.y *= inv; x0.z *= inv; x0.w *= inv;
        x1.x *= inv; x1.y *= inv; x1.z *= inv; x1.w *= inv;
        x2.x *= inv; x2.y *= inv; x2.z *= inv; x2.w *= inv;
        x3.x *= inv; x3.y *= inv; x3.z *= inv; x3.w *= inv;
        row[lane] = x0; row[lane + 32] = x1; row[lane + 64] = x2; row[lane + 96] = x3;
    }
    __syncthreads();

    // write normalized attn
    for (int i = tid; i < 32 * 128; i += 256) {
        int r = i >> 7, c = i & 127;
        *(float4*)&arow[(size_t)r * SS + c * 4] = *(const float4*)&sc[r * SCP + c * 4];
    }

    // AV: out tile 32(t) x 64(d); threads 0..127 compute 4x4 (f32x2 pairs)
    const float* Vg = g_V + (size_t)bh * SS * DH;
    const int tx = tid & 15;    // d/4
    const int ty = tid >> 4;    // t/4 (0..7 for tid<128)
    unsigned long long acc[4][2];
#pragma unroll
    for (int i = 0; i < 4; i++) { acc[i][0] = 0ull; acc[i][1] = 0ull; }

    for (int s0c = 0; s0c < SS; s0c += 32) {
        __syncthreads();
        for (int i = tid; i < 512; i += 256) {
            int rr = i >> 4, cc = i & 15;
            *(float4*)&Bs[rr * 68 + cc * 4] = *(const float4*)&Vg[(size_t)(s0c + rr) * DH + cc * 4];
        }
        __syncthreads();
        if (tid < 128) {
#pragma unroll 8
            for (int kk = 0; kk < 32; kk++) {
                ulonglong2 b2 = *(const ulonglong2*)&Bs[kk * 68 + tx * 4];
#pragma unroll
                for (int i = 0; i < 4; i++) {
                    float a = sc[(size_t)(ty * 4 + i) * SCP + s0c + kk];
                    unsigned long long aa = pack2(a, a);
                    acc[i][0] = fma2(aa, b2.x, acc[i][0]);
                    acc[i][1] = fma2(aa, b2.y, acc[i][1]);
                }
            }
        }
    }

    if (tid < 128) {
        const int b = bh >> 2, h = bh & 3;
#pragma unroll
        for (int i = 0; i < 4; i++) {
            int t = t0 + ty * 4 + i;
            float2 c01 = unpack2(acc[i][0]);
            float2 c23 = unpack2(acc[i][1]);
            *(float4*)&g_att[((size_t)(b * TT + t)) * DM + h * DH + tx * 4] =
                make_float4(c01.x, c01.y, c23.x, c23.y);
        }
    }
}

// ---------------------------------------------------------------------------
extern "C" void kernel_launch(void* const* d_in, const int* in_sizes, int n_in,
                              void* d_out, int out_size) {
    const float* query = (const float*)d_in[0];
    const float* key   = (const float*)d_in[1];
    const float* value = (const float*)d_in[2];
    const float* w_q   = (const float*)d_in[3];
    const float* w_k   = (const float*)d_in[4];
    const float* w_v   = (const float*)d_in[5];
    const float* v_a   = (const float*)d_in[6];
    const float* w_o   = (const float*)d_in[7];

    float* out  = (float*)d_out;
    float* attn = out + (size_t)BB * TT * DM;

    // Q/K/V projections in one launch
    proj_kernel<<<dim3(32, 4, 3), 128>>>(query, key, value, w_q, w_k, w_v);

    // additive scores -> attn region (raw)
    scores_kernel<<<dim3(BHN, TT / 32, SS / 128), 256>>>(v_a, attn);

    // fused softmax + AV
    const int dyn = (32 * SCP + 32 * 68) * sizeof(float);   // 74752 B
    cudaFuncSetAttribute(softmax_av_kernel,
                         cudaFuncAttributeMaxDynamicSharedMemorySize, dyn);
    softmax_av_kernel<<<dim3(BHN, TT / 32), 256, dyn>>>(attn);

    // output projection
    out_kernel<<<dim3(32, 4), 128>>>(w_o, out);
}

// round 3
// speedup vs baseline: 1.4376x; 1.2371x over previous
#include <cuda_runtime.h>
#include <cuda_fp16.h>

#define DM 256
#define NH 4
#define DH 64
#define BB 4
#define TT 512
#define SS 512
#define BHN 16

// Scratch (no allocs -> device globals)
__device__ unsigned int g_Qh[BHN * TT * 32];  // half2 [bh][t][d/2]
__device__ unsigned int g_Kh[BHN * SS * 32];  // half2 [bh][s][d/2]
__device__ float g_V[BHN * SS * DH];          // f32   [bh][s][d]
__device__ float g_att[BB * TT * DM];         // attended [b][t][h*64+d]

// ---- packed helpers -------------------------------------------------------
__device__ __forceinline__ unsigned long long pack2(float x, float y) {
    unsigned long long r;
    asm("mov.b64 %0, {%1, %2};" : "=l"(r) : "f"(x), "f"(y));
    return r;
}
__device__ __forceinline__ float2 unpack2(unsigned long long v) {
    float2 r;
    asm("mov.b64 {%0, %1}, %2;" : "=f"(r.x), "=f"(r.y) : "l"(v));
    return r;
}
__device__ __forceinline__ unsigned long long fma2(unsigned long long a,
                                                   unsigned long long b,
                                                   unsigned long long c) {
    unsigned long long d;
    asm("fma.rn.f32x2 %0, %1, %2, %3;" : "=l"(d) : "l"(a), "l"(b), "l"(c));
    return d;
}
__device__ __forceinline__ unsigned int htanh2(unsigned int x) {
    unsigned int y;
    asm("tanh.approx.f16x2 %0, %1;" : "=r"(y) : "r"(x));
    return y;
}
__device__ __forceinline__ unsigned int hadd2u(unsigned int a, unsigned int b) {
    unsigned int y;
    asm("add.rn.f16x2 %0, %1, %2;" : "=r"(y) : "r"(a), "r"(b));
    return y;
}
__device__ __forceinline__ float2 h2f2(unsigned int h) {
    __half2 v = *reinterpret_cast<__half2*>(&h);
    return __half22float2(v);
}

// 8-element weighted tanh dot: sum_j v[j]*tanh(q[j]+k[j]) for 8 halves
__device__ __forceinline__ float dot8(uint4 q, uint4 k, float4 v0, float4 v1) {
    float2 t0 = h2f2(htanh2(hadd2u(q.x, k.x)));
    float2 t1 = h2f2(htanh2(hadd2u(q.y, k.y)));
    float2 t2 = h2f2(htanh2(hadd2u(q.z, k.z)));
    float2 t3 = h2f2(htanh2(hadd2u(q.w, k.w)));
    float a = v0.x * t0.x + v0.y * t0.y + v0.z * t1.x + v0.w * t1.y;
    a += v1.x * t2.x + v1.y * t2.y + v1.z * t3.x + v1.w * t3.y;
    return a;
}

// ---------------------------------------------------------------------------
// GEMM: C[m][n] = sum_k A[m][k]*W[n][k]. 64x64 tile, 256 thr, 4x4 micro,
// double-buffered smem with one-chunk-ahead LDG prefetch.
// mode 0: -> g_Qh(h16)  1: -> g_Kh(h16)  2: -> g_V(f32)  3: g_att @ w_o.T -> C
// ---------------------------------------------------------------------------
__global__ __launch_bounds__(256) void gemm_kernel(const float* __restrict__ q_in,
                                                   const float* __restrict__ k_in,
                                                   const float* __restrict__ v_in,
                                                   const float* __restrict__ w_q,
                                                   const float* __restrict__ w_k,
                                                   const float* __restrict__ w_v,
                                                   float* __restrict__ C,
                                                   int mode_base) {
    __shared__ float Ast[2][16 * 68];
    __shared__ float Wst[2][16 * 68];

    const int mode = (mode_base == 3) ? 3 : (int)blockIdx.z;
    const float* A = (mode == 0) ? q_in : (mode == 1) ? k_in : (mode == 2) ? v_in : g_att;
    const float* W = (mode == 0) ? w_q : (mode == 1) ? w_k : (mode == 2) ? w_v : /*w_o*/ q_in;

    const int m0 = blockIdx.x * 64;
    const int n0 = blockIdx.y * 64;
    const int tid = threadIdx.x;
    const int tx = tid & 15;
    const int ty = tid >> 4;

    const int lr = tid >> 2;          // 0..63 row within tile
    const int lc = (tid & 3) * 4;     // 0..12 k within chunk
    const float* Aptr = A + (size_t)(m0 + lr) * DM + lc;
    const float* Wptr = W + (size_t)(n0 + lr) * DM + lc;

    unsigned long long acc[4][2];
#pragma unroll
    for (int i = 0; i < 4; i++) { acc[i][0] = 0ull; acc[i][1] = 0ull; }

    // prologue: chunk0 -> buf0, prefetch chunk1
    float4 ra = *(const float4*)Aptr;
    float4 rw = *(const float4*)Wptr;
#pragma unroll
    for (int j = 0; j < 4; j++) {
        Ast[0][(lc + j) * 68 + lr] = ((const float*)&ra)[j];
        Wst[0][(lc + j) * 68 + lr] = ((const float*)&rw)[j];
    }
    ra = *(const float4*)(Aptr + 16);
    rw = *(const float4*)(Wptr + 16);

#pragma unroll 1
    for (int c = 0; c < 16; c++) {
        const int p = c & 1;
        __syncthreads();
        if (c < 15) {
#pragma unroll
            for (int j = 0; j < 4; j++) {
                Ast[p ^ 1][(lc + j) * 68 + lr] = ((const float*)&ra)[j];
                Wst[p ^ 1][(lc + j) * 68 + lr] = ((const float*)&rw)[j];
            }
        }
        if (c < 14) {
            ra = *(const float4*)(Aptr + (c + 2) * 16);
            rw = *(const float4*)(Wptr + (c + 2) * 16);
        }
#pragma unroll
        for (int kk = 0; kk < 16; kk++) {
            float4 a4 = *(const float4*)&Ast[p][kk * 68 + ty * 4];
            ulonglong2 w2 = *(const ulonglong2*)&Wst[p][kk * 68 + tx * 4];
            unsigned long long aa;
            aa = pack2(a4.x, a4.x); acc[0][0] = fma2(aa, w2.x, acc[0][0]); acc[0][1] = fma2(aa, w2.y, acc[0][1]);
            aa = pack2(a4.y, a4.y); acc[1][0] = fma2(aa, w2.x, acc[1][0]); acc[1][1] = fma2(aa, w2.y, acc[1][1]);
            aa = pack2(a4.z, a4.z); acc[2][0] = fma2(aa, w2.x, acc[2][0]); acc[2][1] = fma2(aa, w2.y, acc[2][1]);
            aa = pack2(a4.w, a4.w); acc[3][0] = fma2(aa, w2.x, acc[3][0]); acc[3][1] = fma2(aa, w2.y, acc[3][1]);
        }
    }

    // epilogues
    if (mode <= 1) {
        unsigned int* dst = (mode == 0) ? g_Qh : g_Kh;
        const int hh = n0 >> 6;   // n0 is a multiple of 64 -> d = tx*4
#pragma unroll
        for (int i = 0; i < 4; i++) {
            int m = m0 + ty * 4 + i;
            int bb = m >> 9, t = m & 511;
            float2 c01 = unpack2(acc[i][0]);
            float2 c23 = unpack2(acc[i][1]);
            __half2 h0 = __floats2half2_rn(c01.x, c01.y);
            __half2 h1 = __floats2half2_rn(c23.x, c23.y);
            uint2 u = make_uint2(*(unsigned int*)&h0, *(unsigned int*)&h1);
            *(uint2*)&dst[((size_t)(bb * NH + hh) * TT + t) * 32 + tx * 2] = u;
        }
    } else if (mode == 2) {
        const int hh = n0 >> 6;
#pragma unroll
        for (int i = 0; i < 4; i++) {
            int m = m0 + ty * 4 + i;
            int bb = m >> 9, t = m & 511;
            float2 c01 = unpack2(acc[i][0]);
            float2 c23 = unpack2(acc[i][1]);
            *(float4*)&g_V[((size_t)(bb * NH + hh) * TT + t) * DH + tx * 4] =
                make_float4(c01.x, c01.y, c23.x, c23.y);
        }
    } else {
#pragma unroll
        for (int i = 0; i < 4; i++) {
            int m = m0 + ty * 4 + i;
            float2 c01 = unpack2(acc[i][0]);
            float2 c23 = unpack2(acc[i][1]);
            *(float4*)&C[(size_t)m * DM + n0 + tx * 4] =
                make_float4(c01.x, c01.y, c23.x, c23.y);
        }
    }
}

// ---------------------------------------------------------------------------
// Fused scores(tanh, h16) + softmax + AV. Block = (bh, 32 t rows), full S=512.
// Phase 1: lane = t-row; warp w owns s in [w*64, w*64+64); q row in registers.
// Phase 2: softmax rows in smem. Phase 3: write attn. Phase 4: AV -> g_att.
// ---------------------------------------------------------------------------
#define SCP 516
__global__ __launch_bounds__(256, 2) void attn_fused_kernel(const float* __restrict__ v_a,
                                                            float* __restrict__ attn) {
    extern __shared__ float sm[];
    float* sc = sm;              // 32 * 516
    float* Bs = sm + 32 * SCP;   // 32 * 68

    const int bh = blockIdx.x;
    const int t0 = blockIdx.y * 32;
    const int h = bh & 3;
    const int tid = threadIdx.x;
    const int lane = tid & 31;
    const int w = tid >> 5;

    // ---- Phase 1: scores -> sc --------------------------------------------
    {
        uint4 qreg[8];
        const uint4* qg = (const uint4*)(g_Qh + ((size_t)bh * TT + t0 + lane) * 32);
#pragma unroll
        for (int i = 0; i < 8; i++) qreg[i] = qg[i];

        const float4* va4 = (const float4*)(v_a + h * DH);

#pragma unroll 1
        for (int g = 0; g < 16; g++) {
            const int sl = w * 64 + g * 4;
            const uint4* K0 = (const uint4*)(g_Kh + ((size_t)bh * SS + sl) * 32);
            const uint4* K1 = K0 + 8;
            const uint4* K2 = K0 + 16;
            const uint4* K3 = K0 + 24;
            float a0 = 0.f, a1 = 0.f, a2 = 0.f, a3 = 0.f;
#pragma unroll
            for (int i = 0; i < 8; i++) {
                float4 v0 = __ldg(&va4[2 * i]);
                float4 v1 = __ldg(&va4[2 * i + 1]);
                uint4 q = qreg[i];
                a0 += dot8(q, K0[i], v0, v1);
                a1 += dot8(q, K1[i], v0, v1);
                a2 += dot8(q, K2[i], v0, v1);
                a3 += dot8(q, K3[i], v0, v1);
            }
            *(float4*)&sc[lane * SCP + sl] =
                make_float4(a0 * 0.125f, a1 * 0.125f, a2 * 0.125f, a3 * 0.125f);
        }
    }
    __syncthreads();

    // ---- Phase 2: softmax (warp w -> rows w*4..w*4+3) -----------------------
#pragma unroll 1
    for (int q = 0; q < 4; q++) {
        int r = w * 4 + q;
        float4* row = (float4*)&sc[r * SCP];
        float4 x0 = row[lane], x1 = row[lane + 32], x2 = row[lane + 64], x3 = row[lane + 96];
        float m = fmaxf(fmaxf(fmaxf(x0.x, x0.y), fmaxf(x0.z, x0.w)),
                        fmaxf(fmaxf(x1.x, x1.y), fmaxf(x1.z, x1.w)));
        m = fmaxf(m, fmaxf(fmaxf(fmaxf(x2.x, x2.y), fmaxf(x2.z, x2.w)),
                           fmaxf(fmaxf(x3.x, x3.y), fmaxf(x3.z, x3.w))));
#pragma unroll
        for (int o = 16; o; o >>= 1) m = fmaxf(m, __shfl_xor_sync(0xffffffffu, m, o));
        x0.x = __expf(x0.x - m); x0.y = __expf(x0.y - m); x0.z = __expf(x0.z - m); x0.w = __expf(x0.w - m);
        x1.x = __expf(x1.x - m); x1.y = __expf(x1.y - m); x1.z = __expf(x1.z - m); x1.w = __expf(x1.w - m);
        x2.x = __expf(x2.x - m); x2.y = __expf(x2.y - m); x2.z = __expf(x2.z - m); x2.w = __expf(x2.w - m);
        x3.x = __expf(x3.x - m); x3.y = __expf(x3.y - m); x3.z = __expf(x3.z - m); x3.w = __expf(x3.w - m);
        float s = (x0.x + x0.y + x0.z + x0.w) + (x1.x + x1.y + x1.z + x1.w)
                + (x2.x + x2.y + x2.z + x2.w) + (x3.x + x3.y + x3.z + x3.w);
#pragma unroll
        for (int o = 16; o; o >>= 1) s += __shfl_xor_sync(0xffffffffu, s, o);
        float inv = 1.0f / s;
        x0.x *= inv; x0.y *= inv; x0.z *= inv; x0.w *= inv;
        x1.x *= inv; x1.y *= inv; x1.z *= inv; x1.w *= inv;
        x2.x *= inv; x2.y *= inv; x2.z *= inv; x2.w *= inv;
        x3.x *= inv; x3.y *= inv; x3.z *= inv; x3.w *= inv;
        row[lane] = x0; row[lane + 32] = x1; row[lane + 64] = x2; row[lane + 96] = x3;
    }
    __syncthreads();

    // ---- Phase 3: write attn ------------------------------------------------
    {
        float* arow = attn + ((size_t)bh * TT + t0) * SS;
        for (int i = tid; i < 32 * 128; i += 256) {
            int r = i >> 7, c = i & 127;
            *(float4*)&arow[(size_t)r * SS + c * 4] = *(const float4*)&sc[r * SCP + c * 4];
        }
    }

    // ---- Phase 4: AV (32t x 64d, 256 thr, micro 2t x 4d) --------------------
    const float* Vg = g_V + (size_t)bh * SS * DH;
    const int tx = tid & 15;    // d/4
    const int tyy = tid >> 4;   // t/2  (0..15)
    unsigned long long acc[2][2];
    acc[0][0] = acc[0][1] = acc[1][0] = acc[1][1] = 0ull;

#pragma unroll 1
    for (int s0 = 0; s0 < SS; s0 += 32) {
        __syncthreads();
        for (int i = tid; i < 512; i += 256) {
            int rr = i >> 4, cc = i & 15;
            *(float4*)&Bs[rr * 68 + cc * 4] = *(const float4*)&Vg[(size_t)(s0 + rr) * DH + cc * 4];
        }
        __syncthreads();
#pragma unroll 8
        for (int kk = 0; kk < 32; kk++) {
            ulonglong2 b2 = *(const ulonglong2*)&Bs[kk * 68 + tx * 4];
            float a0 = sc[(size_t)(tyy * 2) * SCP + s0 + kk];
            float a1 = sc[(size_t)(tyy * 2 + 1) * SCP + s0 + kk];
            unsigned long long aa;
            aa = pack2(a0, a0); acc[0][0] = fma2(aa, b2.x, acc[0][0]); acc[0][1] = fma2(aa, b2.y, acc[0][1]);
            aa = pack2(a1, a1); acc[1][0] = fma2(aa, b2.x, acc[1][0]); acc[1][1] = fma2(aa, b2.y, acc[1][1]);
        }
    }

    {
        const int b = bh >> 2;
#pragma unroll
        for (int i = 0; i < 2; i++) {
            int t = t0 + tyy * 2 + i;
            float2 c01 = unpack2(acc[i][0]);
            float2 c23 = unpack2(acc[i][1]);
            *(float4*)&g_att[((size_t)(b * TT + t)) * DM + h * DH + tx * 4] =
                make_float4(c01.x, c01.y, c23.x, c23.y);
        }
    }
}

// ---------------------------------------------------------------------------
extern "C" void kernel_launch(void* const* d_in, const int* in_sizes, int n_in,
                              void* d_out, int out_size) {
    const float* query = (const float*)d_in[0];
    const float* key   = (const float*)d_in[1];
    const float* value = (const float*)d_in[2];
    const float* w_q   = (const float*)d_in[3];
    const float* w_k   = (const float*)d_in[4];
    const float* w_v   = (const float*)d_in[5];
    const float* v_a   = (const float*)d_in[6];
    const float* w_o   = (const float*)d_in[7];

    float* out  = (float*)d_out;
    float* attn = out + (size_t)BB * TT * DM;

    // Q/K/V projections (one launch, z = which)
    gemm_kernel<<<dim3(32, 4, 3), 256>>>(query, key, value, w_q, w_k, w_v, nullptr, 0);

    // fused additive-attention (scores + softmax + AV)
    const int dyn = (32 * SCP + 32 * 68) * sizeof(float);   // ~74.8 KB
    cudaFuncSetAttribute(attn_fused_kernel,
                         cudaFuncAttributeMaxDynamicSharedMemorySize, dyn);
    attn_fused_kernel<<<dim3(BHN, TT / 32), 256, dyn>>>(v_a, attn);

    // output projection: out = g_att @ w_o.T   (w_o passed via q_in slot)
    gemm_kernel<<<dim3(32, 4, 1), 256>>>(w_o, nullptr, nullptr, nullptr, nullptr, nullptr, out, 3);
}